// round 7
// baseline (speedup 1.0000x reference)
#include <cuda_runtime.h>
#include <cstdint>
#include <cstddef>

#define HLD 132
#define HSZ (128 * HLD)
#define SMEM_BYTES ((3 * HSZ + 640 + 512) * 4)

// ---- static device scratch (no allocation allowed) ----
__device__ __align__(16) float g_Wsw[131072];  // swizzled tf32 [g][half][kt][lane][nt][2]
__device__ float g_gb[512];
__device__ float g_ca[128 * 128], g_cb[128 * 128], g_cc[128 * 128];
__device__ float g_mom[128 * 5];
__device__ float g_mu2[128 * 5], g_rs2[128 * 5];

// ---- helpers ----
__device__ __forceinline__ uint32_t tf32u(float f) {
  uint32_t u;
  asm("cvt.rna.tf32.f32 %0,%1;" : "=r"(u) : "f"(f));
  return u;
}
__device__ __forceinline__ float tanh_ap(float x) {
  float y;
  asm("tanh.approx.f32 %0,%1;" : "=f"(y) : "f"(x));
  return y;
}
__device__ __forceinline__ float sig_ap(float x) {
  return fmaf(tanh_ap(0.5f * x), 0.5f, 0.5f);
}
__device__ __forceinline__ void mma8(float (&d)[4], uint32_t a0, uint32_t a1,
                                     uint32_t a2, uint32_t a3, float b0, float b1) {
  asm volatile(
      "mma.sync.aligned.m16n8k8.row.col.f32.tf32.tf32.f32 "
      "{%0,%1,%2,%3},{%4,%5,%6,%7},{%8,%9},{%0,%1,%2,%3};\n"
      : "+f"(d[0]), "+f"(d[1]), "+f"(d[2]), "+f"(d[3])
      : "r"(a0), "r"(a1), "r"(a2), "r"(a3), "r"(__float_as_uint(b0)),
        "r"(__float_as_uint(b1)));
}

// 16 k-tiles of the chunk GEMM. A fp32 in SMEM (hi/lo split at load), B = swizzled
// tf32 weights (LDG.128). acc[8 ntiles][4].
__device__ __forceinline__ void k16(const float* __restrict__ A,
                                    const float4* __restrict__ w4, int r0, int kl,
                                    float (&acc)[8][4]) {
#pragma unroll 2
  for (int kt = 0; kt < 16; kt++) {
    const float* ap = A + kt * 8 + kl;
    float v0 = ap[r0 * HLD], v1 = ap[(r0 + 8) * HLD];
    float v2 = ap[r0 * HLD + 4], v3 = ap[(r0 + 8) * HLD + 4];
    uint32_t h0 = tf32u(v0), h1 = tf32u(v1), h2 = tf32u(v2), h3 = tf32u(v3);
    uint32_t l0 = tf32u(v0 - __uint_as_float(h0));
    uint32_t l1 = tf32u(v1 - __uint_as_float(h1));
    uint32_t l2 = tf32u(v2 - __uint_as_float(h2));
    uint32_t l3 = tf32u(v3 - __uint_as_float(h3));
    const float4* q = w4 + kt * 128;
    float4 q0 = q[0], q1 = q[1], q2 = q[2], q3 = q[3];
    mma8(acc[0], l0, l1, l2, l3, q0.x, q0.y);
    mma8(acc[1], l0, l1, l2, l3, q0.z, q0.w);
    mma8(acc[2], l0, l1, l2, l3, q1.x, q1.y);
    mma8(acc[3], l0, l1, l2, l3, q1.z, q1.w);
    mma8(acc[4], l0, l1, l2, l3, q2.x, q2.y);
    mma8(acc[5], l0, l1, l2, l3, q2.z, q2.w);
    mma8(acc[6], l0, l1, l2, l3, q3.x, q3.y);
    mma8(acc[7], l0, l1, l2, l3, q3.z, q3.w);
    mma8(acc[0], h0, h1, h2, h3, q0.x, q0.y);
    mma8(acc[1], h0, h1, h2, h3, q0.z, q0.w);
    mma8(acc[2], h0, h1, h2, h3, q1.x, q1.y);
    mma8(acc[3], h0, h1, h2, h3, q1.z, q1.w);
    mma8(acc[4], h0, h1, h2, h3, q2.x, q2.y);
    mma8(acc[5], h0, h1, h2, h3, q2.z, q2.w);
    mma8(acc[6], h0, h1, h2, h3, q3.x, q3.y);
    mma8(acc[7], h0, h1, h2, h3, q3.z, q3.w);
  }
}

template <int G, int HALF>
__device__ __forceinline__ void chunk_gemm(const float* __restrict__ E,
                                           const float* __restrict__ Hc, int r0,
                                           int lane, float (&acc)[8][4]) {
#pragma unroll
  for (int n = 0; n < 8; n++) {
    acc[n][0] = 0.f; acc[n][1] = 0.f; acc[n][2] = 0.f; acc[n][3] = 0.f;
  }
  const float4* wb =
      reinterpret_cast<const float4*>(g_Wsw) + ((G * 2 + HALF) * 1024 + lane) * 4;
  k16(E, wb, r0, lane & 3, acc);        // k 0..127  (e part)
  k16(Hc, wb + 2048, r0, lane & 3, acc);// k 128..255 (h part)
}

// One 64-cell half: I -> G -> F -> O. c in registers; writes h (SMEM) + z2 partials.
template <int HALF>
__device__ __forceinline__ void process_half(
    const float* __restrict__ E, const float* __restrict__ Hc, float* __restrict__ Hn,
    const float* __restrict__ ws, const float* __restrict__ gbs, int r0, int lane,
    float (&ch)[8][4], float (&zA)[5], float (&zB)[5]) {
  float acc[8][4], ig[8][4];
  const int cb0 = (HALF << 6) + 2 * (lane & 3);
  chunk_gemm<0, HALF>(E, Hc, r0, lane, acc);  // i-gate
#pragma unroll
  for (int nt = 0; nt < 8; nt++) {
    float2 gv = *reinterpret_cast<const float2*>(gbs + cb0 + nt * 8);
    ig[nt][0] = sig_ap(acc[nt][0] + gv.x);
    ig[nt][1] = sig_ap(acc[nt][1] + gv.y);
    ig[nt][2] = sig_ap(acc[nt][2] + gv.x);
    ig[nt][3] = sig_ap(acc[nt][3] + gv.y);
  }
  chunk_gemm<2, HALF>(E, Hc, r0, lane, acc);  // g-gate
#pragma unroll
  for (int nt = 0; nt < 8; nt++) {
    float2 gv = *reinterpret_cast<const float2*>(gbs + 256 + cb0 + nt * 8);
    ig[nt][0] *= tanh_ap(acc[nt][0] + gv.x);
    ig[nt][1] *= tanh_ap(acc[nt][1] + gv.y);
    ig[nt][2] *= tanh_ap(acc[nt][2] + gv.x);
    ig[nt][3] *= tanh_ap(acc[nt][3] + gv.y);
  }
  chunk_gemm<1, HALF>(E, Hc, r0, lane, acc);  // f-gate
#pragma unroll
  for (int nt = 0; nt < 8; nt++) {
    float2 gv = *reinterpret_cast<const float2*>(gbs + 128 + cb0 + nt * 8);
    ch[nt][0] = fmaf(sig_ap(acc[nt][0] + gv.x), ch[nt][0], ig[nt][0]);
    ch[nt][1] = fmaf(sig_ap(acc[nt][1] + gv.y), ch[nt][1], ig[nt][1]);
    ch[nt][2] = fmaf(sig_ap(acc[nt][2] + gv.x), ch[nt][2], ig[nt][2]);
    ch[nt][3] = fmaf(sig_ap(acc[nt][3] + gv.y), ch[nt][3], ig[nt][3]);
  }
  chunk_gemm<3, HALF>(E, Hc, r0, lane, acc);  // o-gate
#pragma unroll
  for (int nt = 0; nt < 8; nt++) {
    float2 gv = *reinterpret_cast<const float2*>(gbs + 384 + cb0 + nt * 8);
    float h00 = sig_ap(acc[nt][0] + gv.x) * tanh_ap(ch[nt][0]);
    float h01 = sig_ap(acc[nt][1] + gv.y) * tanh_ap(ch[nt][1]);
    float h10 = sig_ap(acc[nt][2] + gv.x) * tanh_ap(ch[nt][2]);
    float h11 = sig_ap(acc[nt][3] + gv.y) * tanh_ap(ch[nt][3]);
    int c0 = cb0 + nt * 8;
    *reinterpret_cast<float2*>(Hn + r0 * HLD + c0) = make_float2(h00, h01);
    *reinterpret_cast<float2*>(Hn + (r0 + 8) * HLD + c0) = make_float2(h10, h11);
#pragma unroll
    for (int o = 0; o < 5; o++) {
      float2 wv = *reinterpret_cast<const float2*>(ws + o * 128 + c0);
      zA[o] = fmaf(h00, wv.x, fmaf(h01, wv.y, zA[o]));
      zB[o] = fmaf(h10, wv.x, fmaf(h11, wv.y, zB[o]));
    }
  }
}

// ---- main recurrent kernel: 256 CTAs x 256 thr, 128 rows/CTA, all 128 steps ----
__global__ void __launch_bounds__(256, 1)
    k_main(const float* __restrict__ x, const float* __restrict__ wout,
           float* __restrict__ out) {
  extern __shared__ float sm_[];
  float* E = sm_;                 // [128][132] embeddings (per step)
  float* Hb = sm_ + HSZ;          // [2][128][132] h double buffer
  float* ws = sm_ + 3 * HSZ;      // [5][128] w_out
  float* gbs = ws + 640;          // [512] gate bias
  const int tid = threadIdx.x, lane = tid & 31, wid = tid >> 5;
  const int bg0 = blockIdx.x << 7;
  const int r0 = (wid << 4) + (lane >> 2);
  for (int i = tid; i < 640; i += 256) ws[i] = wout[i];
  for (int i = tid; i < 512; i += 256) gbs[i] = g_gb[i];
  for (int i = tid; i < HSZ; i += 256) Hb[i] = 0.f;
  float c0r[8][4], c1r[8][4];
#pragma unroll
  for (int n = 0; n < 8; n++)
#pragma unroll
    for (int e = 0; e < 4; e++) { c0r[n][e] = 0.f; c1r[n][e] = 0.f; }
  __syncthreads();
  const int er = tid >> 1, jb = (tid & 1) << 6;
  for (int t = 0; t < 128; t++) {
    // e = relu(ca*x0 + cb*x1 + cc)  (BN1 folded into affine coefficients)
    float2 xv = *reinterpret_cast<const float2*>(
        x + (((size_t)(bg0 + er)) * 128 + t) * 2);
    const float4* ca4 = reinterpret_cast<const float4*>(g_ca + t * 128 + jb);
    const float4* cb4 = reinterpret_cast<const float4*>(g_cb + t * 128 + jb);
    const float4* cc4 = reinterpret_cast<const float4*>(g_cc + t * 128 + jb);
    float* Er = E + er * HLD + jb;
#pragma unroll
    for (int q = 0; q < 16; q++) {
      float4 A4 = ca4[q], B4 = cb4[q], C4 = cc4[q], ev;
      ev.x = fmaxf(fmaf(A4.x, xv.x, fmaf(B4.x, xv.y, C4.x)), 0.f);
      ev.y = fmaxf(fmaf(A4.y, xv.x, fmaf(B4.y, xv.y, C4.y)), 0.f);
      ev.z = fmaxf(fmaf(A4.z, xv.x, fmaf(B4.z, xv.y, C4.z)), 0.f);
      ev.w = fmaxf(fmaf(A4.w, xv.x, fmaf(B4.w, xv.y, C4.w)), 0.f);
      reinterpret_cast<float4*>(Er)[q] = ev;
    }
    __syncthreads();
    const float* Hc = Hb + (t & 1) * HSZ;
    float* Hn = Hb + ((t + 1) & 1) * HSZ;
    float zA[5] = {0.f, 0.f, 0.f, 0.f, 0.f}, zB[5] = {0.f, 0.f, 0.f, 0.f, 0.f};
    process_half<0>(E, Hc, Hn, ws, gbs, r0, lane, c0r, zA, zB);
    process_half<1>(E, Hc, Hn, ws, gbs, r0, lane, c1r, zA, zB);
#pragma unroll
    for (int o = 0; o < 5; o++) {
      zA[o] += __shfl_xor_sync(0xffffffffu, zA[o], 1);
      zA[o] += __shfl_xor_sync(0xffffffffu, zA[o], 2);
      zB[o] += __shfl_xor_sync(0xffffffffu, zB[o], 1);
      zB[o] += __shfl_xor_sync(0xffffffffu, zB[o], 2);
    }
    if ((lane & 3) == 0) {
      size_t oA = (((size_t)(bg0 + r0)) * 128 + t) * 5;
      size_t oB = (((size_t)(bg0 + r0 + 8)) * 128 + t) * 5;
#pragma unroll
      for (int o = 0; o < 5; o++) { out[oA + o] = zA[o]; out[oB + o] = zB[o]; }
    }
    __syncthreads();
  }
}

// ---- prep: batch moments of x per t ----
__global__ void k_moms(const float* __restrict__ x) {
  const int t = blockIdx.x, tid = threadIdx.x, lane = tid & 31, wid = tid >> 5;
  float s[5] = {0.f, 0.f, 0.f, 0.f, 0.f};
  for (int b = tid; b < 32768; b += 256) {
    float2 v = *reinterpret_cast<const float2*>(x + ((size_t)b * 128 + t) * 2);
    s[0] += v.x; s[1] += v.y; s[2] += v.x * v.x; s[3] += v.x * v.y; s[4] += v.y * v.y;
  }
  __shared__ float sh[5][8];
#pragma unroll
  for (int i = 0; i < 5; i++)
    for (int off = 16; off; off >>= 1) s[i] += __shfl_down_sync(0xffffffffu, s[i], off);
  if (lane == 0)
#pragma unroll
    for (int i = 0; i < 5; i++) sh[i][wid] = s[i];
  __syncthreads();
  if (tid == 0) {
#pragma unroll
    for (int i = 0; i < 5; i++) {
      float v = 0.f;
      for (int w = 0; w < 8; w++) v += sh[i][w];
      g_mom[t * 5 + i] = v;
    }
  }
}

// ---- prep: fold BN1 into per-(t,j) affine coefficients ----
__global__ void k_coef(const float* __restrict__ w_emb, const float* __restrict__ b_emb,
                       const float* __restrict__ gamma1,
                       const float* __restrict__ beta1) {
  const int t = blockIdx.x, j = threadIdx.x;
  const float invB = 1.f / 32768.f;
  float m0 = g_mom[t * 5 + 0] * invB, m1 = g_mom[t * 5 + 1] * invB;
  float c00 = g_mom[t * 5 + 2] * invB - m0 * m0;
  float c01 = g_mom[t * 5 + 3] * invB - m0 * m1;
  float c11 = g_mom[t * 5 + 4] * invB - m1 * m1;
  float w0 = w_emb[j * 2], w1 = w_emb[j * 2 + 1], bb = b_emb[j];
  float um = w0 * m0 + w1 * m1 + bb;
  float uv = w0 * w0 * c00 + 2.f * w0 * w1 * c01 + w1 * w1 * c11;
  float r = gamma1[j] * rsqrtf(uv + 1e-5f);
  g_ca[t * 128 + j] = r * w0;
  g_cb[t * 128 + j] = r * w1;
  g_cc[t * 128 + j] = r * (bb - um) + beta1[j];
}

// ---- prep: tf32-round + swizzle combined weights into fragment order ----
__global__ void k_wsw(const float* __restrict__ w_ih, const float* __restrict__ w_hh,
                      const float* __restrict__ b_ih, const float* __restrict__ b_hh) {
  const int idx = blockIdx.x * 256 + threadIdx.x;  // 131072 entries
  if (idx < 512) g_gb[idx] = b_ih[idx] + b_hh[idx];
  int e = idx & 1, nt = (idx >> 1) & 7, lane = (idx >> 4) & 31;
  int kt = (idx >> 9) & 31, gh = idx >> 14;
  int g = gh >> 1, half = gh & 1;
  int k = kt * 8 + (lane & 3) + (e ? 4 : 0);
  int n = g * 128 + half * 64 + nt * 8 + (lane >> 2);
  float v = (k < 128) ? w_ih[n * 128 + k] : w_hh[n * 128 + (k - 128)];
  g_Wsw[idx] = __uint_as_float(tf32u(v));
}

// ---- deferred BN2: stats over batch per (t, o) ----
__global__ void k_bnstats(const float* __restrict__ out) {
  const int t = blockIdx.x, tid = threadIdx.x, lane = tid & 31, wid = tid >> 5;
  float s[5] = {0.f, 0.f, 0.f, 0.f, 0.f}, q[5] = {0.f, 0.f, 0.f, 0.f, 0.f};
  for (int b = tid; b < 32768; b += 256) {
    const float* p = out + ((size_t)b * 128 + t) * 5;
#pragma unroll
    for (int o = 0; o < 5; o++) { float v = p[o]; s[o] += v; q[o] += v * v; }
  }
  __shared__ float sh[10][8];
#pragma unroll
  for (int o = 0; o < 5; o++)
    for (int off = 16; off; off >>= 1) {
      s[o] += __shfl_down_sync(0xffffffffu, s[o], off);
      q[o] += __shfl_down_sync(0xffffffffu, q[o], off);
    }
  if (lane == 0)
#pragma unroll
    for (int o = 0; o < 5; o++) { sh[o][wid] = s[o]; sh[5 + o][wid] = q[o]; }
  __syncthreads();
  if (tid == 0) {
#pragma unroll
    for (int o = 0; o < 5; o++) {
      float S = 0.f, Q = 0.f;
      for (int w = 0; w < 8; w++) { S += sh[o][w]; Q += sh[5 + o][w]; }
      float mu = S / 32768.f, var = Q / 32768.f - mu * mu;
      g_mu2[t * 5 + o] = mu;
      g_rs2[t * 5 + o] = rsqrtf(var + 1e-5f);
    }
  }
}

// ---- deferred BN2: normalize + relu in place ----
__global__ void k_bnnorm(float* __restrict__ out, const float* __restrict__ gamma2,
                         const float* __restrict__ beta2) {
  size_t i = (size_t)blockIdx.x * 256 + threadIdx.x;
  if (i >= (size_t)32768 * 128 * 5) return;
  int o = (int)(i % 5);
  int t = (int)((i / 5) & 127);
  float mu = g_mu2[t * 5 + o], rs = g_rs2[t * 5 + o];
  float v = out[i];
  out[i] = fmaxf(fmaf(gamma2[o] * rs, v - mu, beta2[o]), 0.f);
}

extern "C" void kernel_launch(void* const* d_in, const int* in_sizes, int n_in,
                              void* d_out, int out_size) {
  const float* x = (const float*)d_in[0];
  const float* w_emb = (const float*)d_in[1];
  const float* b_emb = (const float*)d_in[2];
  const float* gamma1 = (const float*)d_in[3];
  const float* beta1 = (const float*)d_in[4];
  const float* w_ih = (const float*)d_in[5];
  const float* w_hh = (const float*)d_in[6];
  const float* b_ih = (const float*)d_in[7];
  const float* b_hh = (const float*)d_in[8];
  const float* w_out = (const float*)d_in[9];
  const float* gamma2 = (const float*)d_in[11];
  const float* beta2 = (const float*)d_in[12];
  float* out = (float*)d_out;
  cudaFuncSetAttribute(k_main, cudaFuncAttributeMaxDynamicSharedMemorySize, SMEM_BYTES);
  k_moms<<<128, 256>>>(x);
  k_coef<<<128, 128>>>(w_emb, b_emb, gamma1, beta1);
  k_wsw<<<512, 256>>>(w_ih, w_hh, b_ih, b_hh);
  k_main<<<256, 256, SMEM_BYTES>>>(x, w_out, out);
  k_bnstats<<<128, 256>>>(out);
  k_bnnorm<<<81920, 256>>>(out, gamma2, beta2);
}